// round 14
// baseline (speedup 1.0000x reference)
#include <cuda_runtime.h>
#include <cstdint>
#include <cstddef>

#define T_STEPS 512
#define BATCH   64
#define EMBED   512
#define HIDDEN  1024
#define G4      4096           // 4*HIDDEN gate rows
#define NCLS    10
#define NCTA    128            // persistent grid (<=148 SMs, co-resident)
#define WSLD    68             // precompute W-tile smem pad
#define PSTR    34             // partial-tile row stride (EVEN: float2-aligned)
#define TILE_F  4096           // floats per tile (16KB)
#define NPERS   6              // pairs with persistent L0 W tiles
// smem: [NPERS persistent W0 tiles][8 working tiles] = 14*16KB = 224KB
#define SMEM_BYTES ((NPERS + 8) * TILE_F * 4)

// ---------------- device-global state (no allocations allowed) ----------------
__device__ float g_X0[(size_t)T_STEPS * G4 * BATCH];   // b0 + x-part of layer0 gates, [t][r][b]
__device__ float g_h0buf[2][HIDDEN * BATCH];           // ping-pong, [k][b]
__device__ float g_h1buf[2][HIDDEN * BATCH];
__device__ unsigned g_cA, g_cB;                        // monotonic barrier counters

// ---------------- packed fp32x2 FMA (bit-identical to 2x scalar FFMA) ----------------
__device__ __forceinline__ float2 ffma2(float2 a, float2 b, float2 c) {
    unsigned long long ua = *reinterpret_cast<unsigned long long*>(&a);
    unsigned long long ub = *reinterpret_cast<unsigned long long*>(&b);
    unsigned long long uc = *reinterpret_cast<unsigned long long*>(&c);
    asm("fma.rn.f32x2 %0, %1, %2, %0;" : "+l"(uc) : "l"(ua), "l"(ub));
    return *reinterpret_cast<float2*>(&uc);
}

__device__ __forceinline__ float sigf(float v) { return 1.0f / (1.0f + expf(-v)); }

// pair barrier: warps 2s, 2s+1 (64 threads), HW barrier id s+1
__device__ __forceinline__ void barp(int s) {
    asm volatile("bar.sync %0, 64;" :: "r"(s + 1) : "memory");
}

// Elected-lane spin on a monotonic counter + acquire fence, then pair barrier.
// (The barp also publishes any smem staging done by the pair just before.)
__device__ __forceinline__ void ctr_wait(unsigned* ctr, unsigned target, int s, int pt) {
    if (pt == 0) {
        while (*(volatile unsigned*)ctr < target) { __nanosleep(32); }
        __threadfence();                // acquire + CCTL.IVALL (SM-wide L1 inval)
    }
    barp(s);
}

// =====================================================================
// Precompute X0[t][r][b] = b0[r] + sum_e emb[x[b][t]][e] * W0[r][e]
// grid (T_STEPS, 64 row-tiles), 128 threads; CTA tile 64 rows x 64 batch
// =====================================================================
__global__ __launch_bounds__(128) void precompute_x0(
    const int* __restrict__ x, const float* __restrict__ emb,
    const float* __restrict__ W0, const float* __restrict__ b0)
{
    __shared__ float Hs[32 * 64];     // embedding tile [kk][b]
    __shared__ float Ws[32 * WSLD];   // W tile transposed [kk][r]
    __shared__ int   sidx[64];

    const int tid   = threadIdx.x;
    const int t     = blockIdx.x;
    const int rbase = blockIdx.y * 64;

    if (tid < 64) sidx[tid] = x[tid * T_STEPS + t];
    __syncthreads();

    const int tb   = tid & 7;
    const int tr   = tid >> 3;
    const int ldrr = tid >> 1;
    const int ldk0 = (tid & 1) * 16;
    const int eb   = tid >> 1;
    const int ek0  = (tid & 1) * 16;

    float2 acc[4][4];
#pragma unroll
    for (int r = 0; r < 4; r++)
#pragma unroll
        for (int p = 0; p < 4; p++) acc[r][p] = make_float2(0.f, 0.f);

    const float* wbase = W0 + (size_t)(rbase + ldrr) * (EMBED + HIDDEN) + ldk0;
    const float* ebase = emb + (size_t)sidx[eb] * EMBED + ek0;

    for (int kt = 0; kt < EMBED; kt += 32) {
#pragma unroll
        for (int i = 0; i < 4; i++) {
            float4 v = *(const float4*)(ebase + kt + i * 4);
            Hs[(ek0 + i * 4 + 0) * 64 + eb] = v.x;
            Hs[(ek0 + i * 4 + 1) * 64 + eb] = v.y;
            Hs[(ek0 + i * 4 + 2) * 64 + eb] = v.z;
            Hs[(ek0 + i * 4 + 3) * 64 + eb] = v.w;
        }
#pragma unroll
        for (int i = 0; i < 4; i++) {
            float4 v = *(const float4*)(wbase + kt + i * 4);
            Ws[(ldk0 + i * 4 + 0) * WSLD + ldrr] = v.x;
            Ws[(ldk0 + i * 4 + 1) * WSLD + ldrr] = v.y;
            Ws[(ldk0 + i * 4 + 2) * WSLD + ldrr] = v.z;
            Ws[(ldk0 + i * 4 + 3) * WSLD + ldrr] = v.w;
        }
        __syncthreads();
#pragma unroll 8
        for (int kk = 0; kk < 32; kk++) {
            float4 wv = *(const float4*)&Ws[kk * WSLD + tr * 4];
            float4 ha = *(const float4*)&Hs[kk * 64 + tb * 8];
            float4 hb = *(const float4*)&Hs[kk * 64 + tb * 8 + 4];
            float2 h2[4] = { {ha.x, ha.y}, {ha.z, ha.w}, {hb.x, hb.y}, {hb.z, hb.w} };
            float  wr[4] = { wv.x, wv.y, wv.z, wv.w };
#pragma unroll
            for (int r = 0; r < 4; r++) {
                float2 w2 = make_float2(wr[r], wr[r]);
#pragma unroll
                for (int p = 0; p < 4; p++) acc[r][p] = ffma2(h2[p], w2, acc[r][p]);
            }
        }
        __syncthreads();
    }

#pragma unroll
    for (int r = 0; r < 4; r++) {
        int row = rbase + tr * 4 + r;
        float bb = b0[row];
        float* o = g_X0 + ((size_t)t * G4 + row) * BATCH + tb * 8;
        *(float4*)o       = make_float4(acc[r][0].x + bb, acc[r][0].y + bb,
                                        acc[r][1].x + bb, acc[r][1].y + bb);
        *(float4*)(o + 4) = make_float4(acc[r][2].x + bb, acc[r][2].y + bb,
                                        acc[r][3].x + bb, acc[r][3].y + bb);
    }
}

// =====================================================================
// Stage a 32-row x 128-k slice of W into smem, repacked [k][32 rows].
// Pair-cooperative: 64 threads; thread = (row rr = pt&31, k-half kc = pt>>5).
// Staged row rr = q*8+i  <->  global gate row q*HIDDEN + cbase + i.
// =====================================================================
__device__ __forceinline__ void stage_W(
    const float* __restrict__ W, int ldw, int col0, int cbase,
    float* Wt, int pt)
{
    const int rr = pt & 31, kc = pt >> 5;
    const int q = rr >> 3, i = rr & 7;
    const float* src = W + (size_t)(q * HIDDEN + cbase + i) * ldw + col0 + kc * 64;
#pragma unroll
    for (int j = 0; j < 16; j++) {
        float4 v = *(const float4*)(src + j * 4);
        int kl = kc * 64 + j * 4;
        Wt[(kl + 0) * 32 + rr] = v.x;
        Wt[(kl + 1) * 32 + rr] = v.y;
        Wt[(kl + 2) * 32 + rr] = v.z;
        Wt[(kl + 3) * 32 + rr] = v.w;
    }
}

// =====================================================================
// 128-k GEMM chunk: warp tile 32 rows x 32 batch, thread 4r x 8b.
// W from smem [k][32] (1 LDS.128/k, dedup to 1 wavefront), software-
// pipelined one k-slot ahead. H from L2 via 2 LDG.128/k, depth-2
// register double buffering.
// =====================================================================
__device__ __forceinline__ void gemm128(
    const float* __restrict__ hp,     // hsrc + koff*64 + hf*32 + bg*8
    const float* __restrict__ wp,     // W tile + rg*4
    float2 (&acc)[4][4])
{
    float4 ha0 = *(const float4*)(hp);
    float4 hb0 = *(const float4*)(hp + 4);
    float4 wv0 = *(const float4*)(wp);
    float4 ha1 = *(const float4*)(hp + 64);
    float4 hb1 = *(const float4*)(hp + 68);
    float4 wv1 = *(const float4*)(wp + 32);

#pragma unroll 4
    for (int kl = 0; kl < 128; kl += 2) {
        {   // compute kl (slot 0)
            float2 h2[4] = { {ha0.x,ha0.y},{ha0.z,ha0.w},{hb0.x,hb0.y},{hb0.z,hb0.w} };
            float  wr[4] = { wv0.x, wv0.y, wv0.z, wv0.w };
#pragma unroll
            for (int r = 0; r < 4; r++) {
                float2 w2 = make_float2(wr[r], wr[r]);
#pragma unroll
                for (int j = 0; j < 4; j++) acc[r][j] = ffma2(h2[j], w2, acc[r][j]);
            }
        }
        int kn = (kl + 2 <= 126) ? kl + 2 : 126;      // clamped tail prefetch
        ha0 = *(const float4*)(hp + kn * 64);
        hb0 = *(const float4*)(hp + kn * 64 + 4);
        wv0 = *(const float4*)(wp + kn * 32);
        {   // compute kl+1 (slot 1)
            float2 h2[4] = { {ha1.x,ha1.y},{ha1.z,ha1.w},{hb1.x,hb1.y},{hb1.z,hb1.w} };
            float  wr[4] = { wv1.x, wv1.y, wv1.z, wv1.w };
#pragma unroll
            for (int r = 0; r < 4; r++) {
                float2 w2 = make_float2(wr[r], wr[r]);
#pragma unroll
                for (int j = 0; j < 4; j++) acc[r][j] = ffma2(h2[j], w2, acc[r][j]);
            }
        }
        int km = (kl + 3 <= 127) ? kl + 3 : 127;
        ha1 = *(const float4*)(hp + km * 64);
        hb1 = *(const float4*)(hp + km * 64 + 4);
        wv1 = *(const float4*)(wp + km * 32);
    }
}

// Write the warp's 32x32 partial into its pair's working-tile slice.
__device__ __forceinline__ void write_partial(float2 (&acc)[4][4], float* part,
                                              int rg, int bg)
{
#pragma unroll
    for (int r = 0; r < 4; r++) {
        float* row = part + (rg * 4 + r) * PSTR + bg * 8;
#pragma unroll
        for (int j = 0; j < 4; j++) *(float2*)(row + j * 2) = acc[r][j];
    }
}

// =====================================================================
// Persistent kernel: CTA owns 8 hidden units (32 gate rows) for BOTH layers.
// 512 threads = 16 warps = 8 K-splits x 2 batch-halves.
// Pairs 0..NPERS-1 keep their L0 W slice resident in smem all 512 steps
// (no per-step L0 staging, no L0 pair barriers for them: gemm reads the
// persistent tile; partial write targets the pair-disjoint working slice;
// the CTA __syncthreads orders it against all cross-warp readers).
// L1 phase keeps R13's asymmetric split: pairs 0-3 wait cA (h0_new),
// pairs 4-7 wait cB (h1_old); chunk-0 W staged before the wait.
// Release = grid_group::sync pattern (CTA barrier + tid0 cumulative fence).
// =====================================================================
__global__ __launch_bounds__(512, 1) void lstm_persistent(
    const float* __restrict__ W0, const float* __restrict__ W1,
    const float* __restrict__ b1)
{
    extern __shared__ float dsm[];    // [NPERS pers W0][8 working tiles]
    float* workb = dsm + NPERS * TILE_F;

    const int tid   = threadIdx.x;
    const int w     = tid >> 5;
    const int lane  = tid & 31;
    const int s     = w >> 1;         // K-split 0..7
    const int hf    = w & 1;          // batch half
    const int pt    = tid & 63;       // pair-local thread
    const int rg    = lane >> 2;      // row group (4 rows)
    const int bg    = lane & 3;       // batch group (8 batch)
    const int cbase = blockIdx.x * 8;
    const int jl    = tid >> 6;       // cell phase: local hidden unit 0..7
    const int b     = tid & 63;       // cell phase: batch lane

    float* Wt_work = workb + s * TILE_F;
    float* part    = Wt_work + hf * (32 * PSTR);
    const float* wp0 = ((s < NPERS) ? (dsm + s * TILE_F) : Wt_work) + rg * 4;
    const float* wp1 = Wt_work + rg * 4;
    const int hoff = hf * 32 + bg * 8;

    float c0 = 0.f, c1 = 0.f;         // register-resident cell state
    float b1r[4];
#pragma unroll
    for (int q = 0; q < 4; q++) b1r[q] = b1[q * HIDDEN + cbase + jl];

    // One-time staging of persistent L0 W tiles (pairs 0..NPERS-1)
    if (s < NPERS)
        stage_W(W0, EMBED + HIDDEN, EMBED + s * 128, cbase, dsm + s * TILE_F, pt);
    __syncthreads();

    for (int t = 0; t < T_STEPS; t++) {
        const int p = t & 1;
        const float* h0_old = g_h0buf[p];
        float*       h0_new = g_h0buf[p ^ 1];
        const float* h1_old = g_h1buf[p];
        float*       h1_new = g_h1buf[p ^ 1];

        // prefetch this thread's X0 gate values (DRAM latency hides under GEMM)
        const float* X0t = g_X0 + (size_t)t * G4 * BATCH;
        float x0r[4];
#pragma unroll
        for (int q = 0; q < 4; q++)
            x0r[q] = X0t[(size_t)(q * HIDDEN + cbase + jl) * BATCH + b];

        // ---- layer 0: gates = X0[t] + W0[:, E:E+H] @ h0_old ----
        float2 acc[4][4];
#pragma unroll
        for (int r = 0; r < 4; r++)
#pragma unroll
            for (int j = 0; j < 4; j++) acc[r][j] = make_float2(0.f, 0.f);

        if (s < NPERS) {
            gemm128(h0_old + (size_t)(s * 128) * 64 + hoff, wp0, acc);
            write_partial(acc, part, rg, bg);       // no barps needed
        } else {
            stage_W(W0, EMBED + HIDDEN, EMBED + s * 128, cbase, Wt_work, pt);
            barp(s);
            gemm128(h0_old + (size_t)(s * 128) * 64 + hoff, wp0, acc);
            barp(s);                  // pair done reading Wt -> alias as partials
            write_partial(acc, part, rg, bg);
        }
        __syncthreads();
        {
            const float* pb = workb + (b >> 5) * (32 * PSTR) + (b & 31);
            float gs[4];
#pragma unroll
            for (int q = 0; q < 4; q++) {
                float v = x0r[q];
#pragma unroll
                for (int ss = 0; ss < 8; ss++)
                    v += pb[ss * TILE_F + (q * 8 + jl) * PSTR];
                gs[q] = v;
            }
            float cn = sigf(gs[1]) * c0 + sigf(gs[0]) * tanhf(gs[2]);
            c0 = cn;
            h0_new[(cbase + jl) * BATCH + b] = sigf(gs[3]) * tanhf(cn);
        }
        __syncthreads();              // all h0_new stores happen-before tid0's fence
        if (tid == 0) { __threadfence(); atomicAdd(&g_cA, 1u); }

        // ---- layer 1: gates = b1 + W1 @ [h0_new ; h1_old] ----
        // Stage chunk 0's W BEFORE the counter wait (ctr_wait's barp publishes).
        // splits 0-3 (h0_new) wait on A; splits 4-7 (h1_old) wait on B.
#pragma unroll
        for (int r = 0; r < 4; r++)
#pragma unroll
            for (int j = 0; j < 4; j++) acc[r][j] = make_float2(0.f, 0.f);

        stage_W(W1, 2 * HIDDEN, s * 256, cbase, Wt_work, pt);
        const float* hsrc;
        if (s < 4) { ctr_wait(&g_cA, (unsigned)(t + 1) * NCTA, s, pt); hsrc = h0_new; }
        else       { ctr_wait(&g_cB, (unsigned)t * NCTA,       s, pt); hsrc = h1_old; }
        const int kb = (s & 3) * 256;
        gemm128(hsrc + (size_t)kb * 64 + hoff, wp1, acc);
        barp(s);
        stage_W(W1, 2 * HIDDEN, s * 256 + 128, cbase, Wt_work, pt);
        barp(s);
        gemm128(hsrc + (size_t)(kb + 128) * 64 + hoff, wp1, acc);
        barp(s);
        write_partial(acc, part, rg, bg);
        __syncthreads();
        {
            const float* pb = workb + (b >> 5) * (32 * PSTR) + (b & 31);
            float gs[4];
#pragma unroll
            for (int q = 0; q < 4; q++) {
                float v = b1r[q];
#pragma unroll
                for (int ss = 0; ss < 8; ss++)
                    v += pb[ss * TILE_F + (q * 8 + jl) * PSTR];
                gs[q] = v;
            }
            float cn = sigf(gs[1]) * c1 + sigf(gs[0]) * tanhf(gs[2]);
            c1 = cn;
            h1_new[(cbase + jl) * BATCH + b] = sigf(gs[3]) * tanhf(cn);
        }
        __syncthreads();              // all h1_new stores happen-before tid0's fence
        if (tid == 0) { __threadfence(); atomicAdd(&g_cB, 1u); }
    }
}

// =====================================================================
// Classifier: out[b][c] = bV[c] + sum_j h1[j][b] * V[c][j]
// (final h1 is g_h1buf[0]: last write at t=511 -> buf[(511&1)^1] = 0)
// =====================================================================
__global__ __launch_bounds__(512) void classify(
    const float* __restrict__ V, const float* __restrict__ bV,
    float* __restrict__ out)
{
    __shared__ float red[512];
    const int c  = blockIdx.x;
    const int tid = threadIdx.x;
    const int b  = tid & 63;
    const int sl = tid >> 6;          // j-slice 0..7
    const float* vr = V + (size_t)c * HIDDEN + sl * 128;
    const float* hp = g_h1buf[0] + (size_t)sl * 128 * BATCH + b;
    float a = 0.f;
#pragma unroll 8
    for (int j = 0; j < 128; j++) a += hp[j * BATCH] * vr[j];
    red[tid] = a;
    __syncthreads();
    if (tid < 64) {
        float ssum = bV[c];
#pragma unroll
        for (int k = 0; k < 8; k++) ssum += red[k * 64 + tid];
        out[tid * NCLS + c] = ssum;
    }
}

__global__ void zero_state()
{
    int i = blockIdx.x * 1024 + threadIdx.x;      // 64 x 1024 = 65536
    g_h0buf[0][i] = 0.f; g_h0buf[1][i] = 0.f;
    g_h1buf[0][i] = 0.f; g_h1buf[1][i] = 0.f;
    if (i == 0) { g_cA = 0u; g_cB = 0u; }
}

// =====================================================================
extern "C" void kernel_launch(void* const* d_in, const int* in_sizes, int n_in,
                              void* d_out, int out_size)
{
    (void)in_sizes; (void)n_in; (void)out_size;
    const int*   x   = (const int*)d_in[0];
    const float* emb = (const float*)d_in[1];
    const float* W0  = (const float*)d_in[2];
    const float* b0  = (const float*)d_in[3];
    const float* W1  = (const float*)d_in[4];
    const float* b1  = (const float*)d_in[5];
    const float* V   = (const float*)d_in[6];
    const float* bV  = (const float*)d_in[7];
    float* out = (float*)d_out;

    cudaFuncSetAttribute(lstm_persistent,
                         cudaFuncAttributeMaxDynamicSharedMemorySize, SMEM_BYTES);

    zero_state<<<64, 1024>>>();
    precompute_x0<<<dim3(T_STEPS, 64), 128>>>(x, emb, W0, b0);
    lstm_persistent<<<NCTA, 512, SMEM_BYTES>>>(W0, W1, b1);
    classify<<<NCLS, BATCH * 8>>>(V, bV, out);
}

// round 15
// speedup vs baseline: 1.0330x; 1.0330x over previous
#include <cuda_runtime.h>
#include <cstdint>
#include <cstddef>

#define T_STEPS 512
#define BATCH   64
#define EMBED   512
#define HIDDEN  1024
#define G4      4096           // 4*HIDDEN gate rows
#define NCLS    10
#define NCTA    128            // persistent grid (<=148 SMs, co-resident)
#define NTHR    256            // threads per CTA (8 warps = 8 K-splits)
#define WSLD    68             // precompute W-tile smem pad
#define PSTR    66             // partial row stride (EVEN: float2-aligned, padded)
#define TILE_F  4096           // floats per warp tile (16KB)
#define SMEM_BYTES (8 * TILE_F * 4)   // 128KB: 8 warp W-tiles / partials

// ---------------- device-global state (no allocations allowed) ----------------
__device__ float g_X0[(size_t)T_STEPS * G4 * BATCH];   // b0 + x-part of layer0 gates, [t][r][b]
__device__ float g_h0buf[2][HIDDEN * BATCH];           // ping-pong, [k][b]
__device__ float g_h1buf[2][HIDDEN * BATCH];
__device__ unsigned g_cA, g_cB;                        // monotonic barrier counters

// ---------------- packed fp32x2 FMA (bit-identical to 2x scalar FFMA) ----------------
__device__ __forceinline__ float2 ffma2(float2 a, float2 b, float2 c) {
    unsigned long long ua = *reinterpret_cast<unsigned long long*>(&a);
    unsigned long long ub = *reinterpret_cast<unsigned long long*>(&b);
    unsigned long long uc = *reinterpret_cast<unsigned long long*>(&c);
    asm("fma.rn.f32x2 %0, %1, %2, %0;" : "+l"(uc) : "l"(ua), "l"(ub));
    return *reinterpret_cast<float2*>(&uc);
}

__device__ __forceinline__ float sigf(float v) { return 1.0f / (1.0f + expf(-v)); }

// Elected-lane spin on a monotonic counter + acquire fence, warp-local.
// The trailing __syncwarp also publishes this warp's own smem staging.
__device__ __forceinline__ void ctr_wait(unsigned* ctr, unsigned target, int lane) {
    if (lane == 0) {
        while (*(volatile unsigned*)ctr < target) { __nanosleep(32); }
        __threadfence();                // acquire + CCTL.IVALL (SM-wide L1 inval)
    }
    __syncwarp();
}

// =====================================================================
// Precompute X0[t][r][b] = b0[r] + sum_e emb[x[b][t]][e] * W0[r][e]
// grid (T_STEPS, 64 row-tiles), 128 threads; CTA tile 64 rows x 64 batch
// =====================================================================
__global__ __launch_bounds__(128) void precompute_x0(
    const int* __restrict__ x, const float* __restrict__ emb,
    const float* __restrict__ W0, const float* __restrict__ b0)
{
    __shared__ float Hs[32 * 64];     // embedding tile [kk][b]
    __shared__ float Ws[32 * WSLD];   // W tile transposed [kk][r]
    __shared__ int   sidx[64];

    const int tid   = threadIdx.x;
    const int t     = blockIdx.x;
    const int rbase = blockIdx.y * 64;

    if (tid < 64) sidx[tid] = x[tid * T_STEPS + t];
    __syncthreads();

    const int tb   = tid & 7;
    const int tr   = tid >> 3;
    const int ldrr = tid >> 1;
    const int ldk0 = (tid & 1) * 16;
    const int eb   = tid >> 1;
    const int ek0  = (tid & 1) * 16;

    float2 acc[4][4];
#pragma unroll
    for (int r = 0; r < 4; r++)
#pragma unroll
        for (int p = 0; p < 4; p++) acc[r][p] = make_float2(0.f, 0.f);

    const float* wbase = W0 + (size_t)(rbase + ldrr) * (EMBED + HIDDEN) + ldk0;
    const float* ebase = emb + (size_t)sidx[eb] * EMBED + ek0;

    for (int kt = 0; kt < EMBED; kt += 32) {
#pragma unroll
        for (int i = 0; i < 4; i++) {
            float4 v = *(const float4*)(ebase + kt + i * 4);
            Hs[(ek0 + i * 4 + 0) * 64 + eb] = v.x;
            Hs[(ek0 + i * 4 + 1) * 64 + eb] = v.y;
            Hs[(ek0 + i * 4 + 2) * 64 + eb] = v.z;
            Hs[(ek0 + i * 4 + 3) * 64 + eb] = v.w;
        }
#pragma unroll
        for (int i = 0; i < 4; i++) {
            float4 v = *(const float4*)(wbase + kt + i * 4);
            Ws[(ldk0 + i * 4 + 0) * WSLD + ldrr] = v.x;
            Ws[(ldk0 + i * 4 + 1) * WSLD + ldrr] = v.y;
            Ws[(ldk0 + i * 4 + 2) * WSLD + ldrr] = v.z;
            Ws[(ldk0 + i * 4 + 3) * WSLD + ldrr] = v.w;
        }
        __syncthreads();
#pragma unroll 8
        for (int kk = 0; kk < 32; kk++) {
            float4 wv = *(const float4*)&Ws[kk * WSLD + tr * 4];
            float4 ha = *(const float4*)&Hs[kk * 64 + tb * 8];
            float4 hb = *(const float4*)&Hs[kk * 64 + tb * 8 + 4];
            float2 h2[4] = { {ha.x, ha.y}, {ha.z, ha.w}, {hb.x, hb.y}, {hb.z, hb.w} };
            float  wr[4] = { wv.x, wv.y, wv.z, wv.w };
#pragma unroll
            for (int r = 0; r < 4; r++) {
                float2 w2 = make_float2(wr[r], wr[r]);
#pragma unroll
                for (int p = 0; p < 4; p++) acc[r][p] = ffma2(h2[p], w2, acc[r][p]);
            }
        }
        __syncthreads();
    }

#pragma unroll
    for (int r = 0; r < 4; r++) {
        int row = rbase + tr * 4 + r;
        float bb = b0[row];
        float* o = g_X0 + ((size_t)t * G4 + row) * BATCH + tb * 8;
        *(float4*)o       = make_float4(acc[r][0].x + bb, acc[r][0].y + bb,
                                        acc[r][1].x + bb, acc[r][1].y + bb);
        *(float4*)(o + 4) = make_float4(acc[r][2].x + bb, acc[r][2].y + bb,
                                        acc[r][3].x + bb, acc[r][3].y + bb);
    }
}

// =====================================================================
// Stage a 32-row x 128-k slice of W into the warp's tile, repacked [k][32r].
// Warp-cooperative: lane rr loads its whole row (128 k, 32 float4s).
// Staged row rr = q*8+i  <->  global gate row q*HIDDEN + cbase + i.
// STS addresses kl*32+rr: lanes consecutive -> conflict-free.
// =====================================================================
__device__ __forceinline__ void stage_W(
    const float* __restrict__ W, int ldw, int col0, int cbase,
    float* Wt, int lane)
{
    const int q = lane >> 3, i = lane & 7;
    const float* src = W + (size_t)(q * HIDDEN + cbase + i) * ldw + col0;
#pragma unroll 8
    for (int j = 0; j < 32; j++) {
        float4 v = *(const float4*)(src + j * 4);
        int kl = j * 4;
        Wt[(kl + 0) * 32 + lane] = v.x;
        Wt[(kl + 1) * 32 + lane] = v.y;
        Wt[(kl + 2) * 32 + lane] = v.z;
        Wt[(kl + 3) * 32 + lane] = v.w;
    }
}

// =====================================================================
// 128-k GEMM chunk: warp tile 32 rows x 64 batch, thread 8r x 8b.
// Per k per WARP: 2 LDS.128 (W, broadcast-dedup) + 2 LDG.128 (H) + 32 FFMA2
// -> LDG/SM/step ~7K instrs (vs 49K before): LSU floor no longer binding.
// Depth-4 register pipeline on both W and H (slot idx unroll-constant).
// =====================================================================
__device__ __forceinline__ void gemm128(
    const float* __restrict__ hp,     // hsrc + koff*64 + bg*8
    const float* __restrict__ wp,     // Wt + rg*8
    float2 (&acc)[8][4])
{
    float4 ha[4], hb[4], wa[4], wb[4];
#pragma unroll
    for (int sl = 0; sl < 4; sl++) {
        ha[sl] = *(const float4*)(hp + sl * 64);
        hb[sl] = *(const float4*)(hp + sl * 64 + 4);
        wa[sl] = *(const float4*)(wp + sl * 32);
        wb[sl] = *(const float4*)(wp + sl * 32 + 4);
    }

#pragma unroll 2
    for (int k = 0; k < 128; k += 4) {
#pragma unroll
        for (int u = 0; u < 4; u++) {
            const int kk = k + u;
            float2 h2[4] = { {ha[u].x, ha[u].y}, {ha[u].z, ha[u].w},
                             {hb[u].x, hb[u].y}, {hb[u].z, hb[u].w} };
            float  wr[8] = { wa[u].x, wa[u].y, wa[u].z, wa[u].w,
                             wb[u].x, wb[u].y, wb[u].z, wb[u].w };
#pragma unroll
            for (int i = 0; i < 8; i++) {
                float2 w2 = make_float2(wr[i], wr[i]);
#pragma unroll
                for (int j = 0; j < 4; j++) acc[i][j] = ffma2(h2[j], w2, acc[i][j]);
            }
            const int kn = (kk + 4 < 128) ? kk + 4 : kk;   // clamped tail reload
            ha[u] = *(const float4*)(hp + kn * 64);
            hb[u] = *(const float4*)(hp + kn * 64 + 4);
            wa[u] = *(const float4*)(wp + kn * 32);
            wb[u] = *(const float4*)(wp + kn * 32 + 4);
        }
    }
}

// Write the warp's 32x64 partial into its own tile (aliased; after syncwarp).
// Row rr = rg*8+i = (gate rg, unit i); cols bg*8..bg*8+7.
__device__ __forceinline__ void write_partial(float2 (&acc)[8][4], float* part,
                                              int rg, int bg)
{
#pragma unroll
    for (int i = 0; i < 8; i++) {
        float* row = part + (rg * 8 + i) * PSTR + bg * 8;
#pragma unroll
        for (int j = 0; j < 4; j++) *(float2*)(row + j * 2) = acc[i][j];
    }
}

// =====================================================================
// Persistent kernel: CTA owns 8 hidden units (32 gate rows) for BOTH layers.
// 256 threads = 8 warps = 8 K-splits; warp tile 32r x 64b, thread 8r x 8b.
// All tile reuse is warp-private -> __syncwarp only (no named barriers).
// Sync skeleton identical to R13: ping-pong h, asymmetric cA/cB waiters,
// grid_group::sync-style release (CTA barrier + tid0 cumulative fence).
// =====================================================================
__global__ __launch_bounds__(NTHR, 1) void lstm_persistent(
    const float* __restrict__ W0, const float* __restrict__ W1,
    const float* __restrict__ b1)
{
    extern __shared__ float dsm[];    // 8 warp tiles of TILE_F floats

    const int tid   = threadIdx.x;
    const int s     = tid >> 5;       // warp = K-split 0..7
    const int lane  = tid & 31;
    const int rg    = lane >> 3;      // gate group: thread's 8 rows = gate rg, units 0..7
    const int bg    = lane & 7;       // batch group (8 batch)
    const int cbase = blockIdx.x * 8;
    const int jl    = tid >> 6;       // cell phase: local hidden unit (cells tid, tid+256)
    const int b     = tid & 63;       // cell phase: batch lane

    float* Wt = dsm + s * TILE_F;
    const float* wp = Wt + rg * 8;

    float c0[2] = {0.f, 0.f}, c1[2] = {0.f, 0.f};  // register cell state (2 cells/thread)
    float b1r[2][4];
#pragma unroll
    for (int u = 0; u < 2; u++)
#pragma unroll
        for (int q = 0; q < 4; q++)
            b1r[u][q] = b1[q * HIDDEN + cbase + (jl + u * 4)];

    for (int t = 0; t < T_STEPS; t++) {
        const int p = t & 1;
        const float* h0_old = g_h0buf[p];
        float*       h0_new = g_h0buf[p ^ 1];
        const float* h1_old = g_h1buf[p];
        float*       h1_new = g_h1buf[p ^ 1];

        // prefetch this thread's X0 gate values (DRAM latency hides under GEMM)
        const float* X0t = g_X0 + (size_t)t * G4 * BATCH;
        float x0r[2][4];
#pragma unroll
        for (int u = 0; u < 2; u++)
#pragma unroll
            for (int q = 0; q < 4; q++)
                x0r[u][q] = X0t[(size_t)(q * HIDDEN + cbase + jl + u * 4) * BATCH + b];

        // ---- layer 0: gates = X0[t] + W0[:, E:E+H] @ h0_old  (128 k per warp) ----
        float2 acc[8][4];
#pragma unroll
        for (int i = 0; i < 8; i++)
#pragma unroll
            for (int j = 0; j < 4; j++) acc[i][j] = make_float2(0.f, 0.f);

        stage_W(W0, EMBED + HIDDEN, EMBED + s * 128, cbase, Wt, lane);
        __syncwarp();
        gemm128(h0_old + (size_t)(s * 128) * 64 + bg * 8, wp, acc);
        __syncwarp();                 // warp done reading Wt -> alias as partial
        write_partial(acc, Wt, rg, bg);
        __syncthreads();
        {
#pragma unroll
            for (int u = 0; u < 2; u++) {
                const int ju = jl + u * 4;
                float gs[4];
#pragma unroll
                for (int q = 0; q < 4; q++) {
                    float v = x0r[u][q];
#pragma unroll
                    for (int ss = 0; ss < 8; ss++)
                        v += dsm[ss * TILE_F + (q * 8 + ju) * PSTR + b];
                    gs[q] = v;
                }
                float cn = sigf(gs[1]) * c0[u] + sigf(gs[0]) * tanhf(gs[2]);
                c0[u] = cn;
                h0_new[(cbase + ju) * BATCH + b] = sigf(gs[3]) * tanhf(cn);
            }
        }
        __syncthreads();              // all h0_new stores happen-before tid0's fence
        if (tid == 0) { __threadfence(); atomicAdd(&g_cA, 1u); }

        // ---- layer 1: gates = b1 + W1 @ [h0_new ; h1_old]  (256 k per warp) ----
        // Stage chunk 0's W BEFORE the counter wait (ctr_wait's syncwarp publishes).
        // warps 0-3 (h0_new) wait on A; warps 4-7 (h1_old) wait on B.
#pragma unroll
        for (int i = 0; i < 8; i++)
#pragma unroll
            for (int j = 0; j < 4; j++) acc[i][j] = make_float2(0.f, 0.f);

        stage_W(W1, 2 * HIDDEN, s * 256, cbase, Wt, lane);
        const float* hsrc;
        int koff;
        if (s < 4) { ctr_wait(&g_cA, (unsigned)(t + 1) * NCTA, lane);
                     hsrc = h0_new; koff = s * 256; }
        else       { ctr_wait(&g_cB, (unsigned)t * NCTA, lane);
                     hsrc = h1_old; koff = (s - 4) * 256; }
        gemm128(hsrc + (size_t)koff * 64 + bg * 8, wp, acc);
        __syncwarp();
        stage_W(W1, 2 * HIDDEN, s * 256 + 128, cbase, Wt, lane);
        __syncwarp();
        gemm128(hsrc + (size_t)(koff + 128) * 64 + bg * 8, wp, acc);
        __syncwarp();
        write_partial(acc, Wt, rg, bg);
        __syncthreads();
        {
#pragma unroll
            for (int u = 0; u < 2; u++) {
                const int ju = jl + u * 4;
                float gs[4];
#pragma unroll
                for (int q = 0; q < 4; q++) {
                    float v = b1r[u][q];
#pragma unroll
                    for (int ss = 0; ss < 8; ss++)
                        v += dsm[ss * TILE_F + (q * 8 + ju) * PSTR + b];
                    gs[q] = v;
                }
                float cn = sigf(gs[1]) * c1[u] + sigf(gs[0]) * tanhf(gs[2]);
                c1[u] = cn;
                h1_new[(cbase + ju) * BATCH + b] = sigf(gs[3]) * tanhf(cn);
            }
        }
        __syncthreads();              // all h1_new stores happen-before tid0's fence
        if (tid == 0) { __threadfence(); atomicAdd(&g_cB, 1u); }
    }
}

// =====================================================================
// Classifier: out[b][c] = bV[c] + sum_j h1[j][b] * V[c][j]
// (final h1 is g_h1buf[0]: last write at t=511 -> buf[(511&1)^1] = 0)
// =====================================================================
__global__ __launch_bounds__(512) void classify(
    const float* __restrict__ V, const float* __restrict__ bV,
    float* __restrict__ out)
{
    __shared__ float red[512];
    const int c  = blockIdx.x;
    const int tid = threadIdx.x;
    const int b  = tid & 63;
    const int sl = tid >> 6;          // j-slice 0..7
    const float* vr = V + (size_t)c * HIDDEN + sl * 128;
    const float* hp = g_h1buf[0] + (size_t)sl * 128 * BATCH + b;
    float a = 0.f;
#pragma unroll 8
    for (int j = 0; j < 128; j++) a += hp[j * BATCH] * vr[j];
    red[tid] = a;
    __syncthreads();
    if (tid < 64) {
        float ssum = bV[c];
#pragma unroll
        for (int k = 0; k < 8; k++) ssum += red[k * 64 + tid];
        out[tid * NCLS + c] = ssum;
    }
}

__global__ void zero_state()
{
    int i = blockIdx.x * 1024 + threadIdx.x;      // 64 x 1024 = 65536
    g_h0buf[0][i] = 0.f; g_h0buf[1][i] = 0.f;
    g_h1buf[0][i] = 0.f; g_h1buf[1][i] = 0.f;
    if (i == 0) { g_cA = 0u; g_cB = 0u; }
}

// =====================================================================
extern "C" void kernel_launch(void* const* d_in, const int* in_sizes, int n_in,
                              void* d_out, int out_size)
{
    (void)in_sizes; (void)n_in; (void)out_size;
    const int*   x   = (const int*)d_in[0];
    const float* emb = (const float*)d_in[1];
    const float* W0  = (const float*)d_in[2];
    const float* b0  = (const float*)d_in[3];
    const float* W1  = (const float*)d_in[4];
    const float* b1  = (const float*)d_in[5];
    const float* V   = (const float*)d_in[6];
    const float* bV  = (const float*)d_in[7];
    float* out = (float*)d_out;

    cudaFuncSetAttribute(lstm_persistent,
                         cudaFuncAttributeMaxDynamicSharedMemorySize, SMEM_BYTES);

    zero_state<<<64, 1024>>>();
    precompute_x0<<<dim3(T_STEPS, 64), 128>>>(x, emb, W0, b0);
    lstm_persistent<<<NCTA, NTHR, SMEM_BYTES>>>(W0, W1, b1);
    classify<<<NCLS, BATCH * 8>>>(V, bV, out);
}

// round 16
// speedup vs baseline: 1.0820x; 1.0474x over previous
#include <cuda_runtime.h>
#include <cstdint>
#include <cstddef>

#define T_STEPS 512
#define BATCH   64
#define EMBED   512
#define HIDDEN  1024
#define G4      4096           // 4*HIDDEN gate rows
#define NCLS    10
#define NCTA    128            // persistent grid (<=148 SMs, co-resident)
#define WSLD    68             // precompute W-tile smem pad
#define PSTR    34             // partial-tile row stride (EVEN: float2-aligned)
#define TILE_F  4096           // floats per pair tile (16KB)
#define SMEM_BYTES (8 * TILE_F * 4)   // 128KB: 8 pair W-tiles / partials

// ---------------- device-global state (no allocations allowed) ----------------
__device__ float g_X0[(size_t)T_STEPS * G4 * BATCH];   // b0 + x-part of layer0 gates, [t][r][b]
__device__ float g_h0buf[2][HIDDEN * BATCH];           // ping-pong, [k][b]
__device__ float g_h1buf[2][HIDDEN * BATCH];
__device__ unsigned g_cA, g_cB;                        // monotonic barrier counters

// ---------------- packed fp32x2 FMA (bit-identical to 2x scalar FFMA) ----------------
__device__ __forceinline__ float2 ffma2(float2 a, float2 b, float2 c) {
    unsigned long long ua = *reinterpret_cast<unsigned long long*>(&a);
    unsigned long long ub = *reinterpret_cast<unsigned long long*>(&b);
    unsigned long long uc = *reinterpret_cast<unsigned long long*>(&c);
    asm("fma.rn.f32x2 %0, %1, %2, %0;" : "+l"(uc) : "l"(ua), "l"(ub));
    return *reinterpret_cast<float2*>(&uc);
}

// ---------------- fast gate nonlinearities (MUFU-based, ~5-7 SASS each) ----------------
// sigma: rel err ~5e-7 (EX2 + RCP at 2^-21). Large |v| saturates cleanly.
__device__ __forceinline__ float sigf(float v) {
    return __fdividef(1.0f, 1.0f + __expf(-v));
}
// tanh(v) = sign(v) * (1-e)/(1+e), e = exp(-2|v|) in (0,1] -> no overflow path.
__device__ __forceinline__ float tanh_fast(float v) {
    float a = fabsf(v);
    float e = __expf(-2.0f * a);
    float t = __fdividef(1.0f - e, 1.0f + e);
    return copysignf(t, v);
}

// pair barrier: warps 2s, 2s+1 (64 threads), HW barrier id s+1
__device__ __forceinline__ void barp(int s) {
    asm volatile("bar.sync %0, 64;" :: "r"(s + 1) : "memory");
}

// Elected-lane spin on a monotonic counter + acquire fence, then pair barrier.
// (The barp also publishes any smem staging done by the pair just before.)
__device__ __forceinline__ void ctr_wait(unsigned* ctr, unsigned target, int s, int pt) {
    if (pt == 0) {
        while (*(volatile unsigned*)ctr < target) { __nanosleep(32); }
        __threadfence();                // acquire + CCTL.IVALL (SM-wide L1 inval)
    }
    barp(s);
}

// =====================================================================
// Precompute X0[t][r][b] = b0[r] + sum_e emb[x[b][t]][e] * W0[r][e]
// grid (T_STEPS, 64 row-tiles), 128 threads; CTA tile 64 rows x 64 batch.
// Blocks with t==0 additionally zero the h state and reset the counters
// (kernel-boundary ordering makes them visible to lstm_persistent).
// =====================================================================
__global__ __launch_bounds__(128) void precompute_x0(
    const int* __restrict__ x, const float* __restrict__ emb,
    const float* __restrict__ W0, const float* __restrict__ b0)
{
    __shared__ float Hs[32 * 64];     // embedding tile [kk][b]
    __shared__ float Ws[32 * WSLD];   // W tile transposed [kk][r]
    __shared__ int   sidx[64];

    const int tid   = threadIdx.x;
    const int t     = blockIdx.x;
    const int rbase = blockIdx.y * 64;

    if (t == 0) {                     // fold of zero_state: 64 blocks cover the state
        int base = blockIdx.y * 1024 + tid * 8;
#pragma unroll
        for (int i2 = 0; i2 < 8; i2++) {
            g_h0buf[0][base + i2] = 0.f; g_h0buf[1][base + i2] = 0.f;
            g_h1buf[0][base + i2] = 0.f; g_h1buf[1][base + i2] = 0.f;
        }
        if (blockIdx.y == 0 && tid == 0) { g_cA = 0u; g_cB = 0u; }
    }

    if (tid < 64) sidx[tid] = x[tid * T_STEPS + t];
    __syncthreads();

    const int tb   = tid & 7;
    const int tr   = tid >> 3;
    const int ldrr = tid >> 1;
    const int ldk0 = (tid & 1) * 16;
    const int eb   = tid >> 1;
    const int ek0  = (tid & 1) * 16;

    float2 acc[4][4];
#pragma unroll
    for (int r = 0; r < 4; r++)
#pragma unroll
        for (int p = 0; p < 4; p++) acc[r][p] = make_float2(0.f, 0.f);

    const float* wbase = W0 + (size_t)(rbase + ldrr) * (EMBED + HIDDEN) + ldk0;
    const float* ebase = emb + (size_t)sidx[eb] * EMBED + ek0;

    for (int kt = 0; kt < EMBED; kt += 32) {
#pragma unroll
        for (int i = 0; i < 4; i++) {
            float4 v = *(const float4*)(ebase + kt + i * 4);
            Hs[(ek0 + i * 4 + 0) * 64 + eb] = v.x;
            Hs[(ek0 + i * 4 + 1) * 64 + eb] = v.y;
            Hs[(ek0 + i * 4 + 2) * 64 + eb] = v.z;
            Hs[(ek0 + i * 4 + 3) * 64 + eb] = v.w;
        }
#pragma unroll
        for (int i = 0; i < 4; i++) {
            float4 v = *(const float4*)(wbase + kt + i * 4);
            Ws[(ldk0 + i * 4 + 0) * WSLD + ldrr] = v.x;
            Ws[(ldk0 + i * 4 + 1) * WSLD + ldrr] = v.y;
            Ws[(ldk0 + i * 4 + 2) * WSLD + ldrr] = v.z;
            Ws[(ldk0 + i * 4 + 3) * WSLD + ldrr] = v.w;
        }
        __syncthreads();
#pragma unroll 8
        for (int kk = 0; kk < 32; kk++) {
            float4 wv = *(const float4*)&Ws[kk * WSLD + tr * 4];
            float4 ha = *(const float4*)&Hs[kk * 64 + tb * 8];
            float4 hb = *(const float4*)&Hs[kk * 64 + tb * 8 + 4];
            float2 h2[4] = { {ha.x, ha.y}, {ha.z, ha.w}, {hb.x, hb.y}, {hb.z, hb.w} };
            float  wr[4] = { wv.x, wv.y, wv.z, wv.w };
#pragma unroll
            for (int r = 0; r < 4; r++) {
                float2 w2 = make_float2(wr[r], wr[r]);
#pragma unroll
                for (int p = 0; p < 4; p++) acc[r][p] = ffma2(h2[p], w2, acc[r][p]);
            }
        }
        __syncthreads();
    }

#pragma unroll
    for (int r = 0; r < 4; r++) {
        int row = rbase + tr * 4 + r;
        float bb = b0[row];
        float* o = g_X0 + ((size_t)t * G4 + row) * BATCH + tb * 8;
        *(float4*)o       = make_float4(acc[r][0].x + bb, acc[r][0].y + bb,
                                        acc[r][1].x + bb, acc[r][1].y + bb);
        *(float4*)(o + 4) = make_float4(acc[r][2].x + bb, acc[r][2].y + bb,
                                        acc[r][3].x + bb, acc[r][3].y + bb);
    }
}

// =====================================================================
// Stage a 32-row x 128-k slice of W into smem, repacked [k][32 rows].
// Pair-cooperative: 64 threads; thread = (row rr = pt&31, k-half kc = pt>>5).
// Staged row rr = q*8+i  <->  global gate row q*HIDDEN + cbase + i.
// =====================================================================
__device__ __forceinline__ void stage_W(
    const float* __restrict__ W, int ldw, int col0, int cbase,
    float* Wt, int pt)
{
    const int rr = pt & 31, kc = pt >> 5;
    const int q = rr >> 3, i = rr & 7;
    const float* src = W + (size_t)(q * HIDDEN + cbase + i) * ldw + col0 + kc * 64;
#pragma unroll
    for (int j = 0; j < 16; j++) {
        float4 v = *(const float4*)(src + j * 4);
        int kl = kc * 64 + j * 4;
        Wt[(kl + 0) * 32 + rr] = v.x;
        Wt[(kl + 1) * 32 + rr] = v.y;
        Wt[(kl + 2) * 32 + rr] = v.z;
        Wt[(kl + 3) * 32 + rr] = v.w;
    }
}

// =====================================================================
// 128-k GEMM chunk: warp tile 32 rows x 32 batch, thread 4r x 8b.
// W from smem [k][32] (1 LDS.128/k, dedup to 1 wavefront), software-
// pipelined one k-slot ahead. H from L2 via 2 LDG.128/k, depth-2
// register double buffering.
// =====================================================================
__device__ __forceinline__ void gemm128(
    const float* __restrict__ hp,     // hsrc + koff*64 + hf*32 + bg*8
    const float* __restrict__ wp,     // Wt + rg*4
    float2 (&acc)[4][4])
{
    float4 ha0 = *(const float4*)(hp);
    float4 hb0 = *(const float4*)(hp + 4);
    float4 wv0 = *(const float4*)(wp);
    float4 ha1 = *(const float4*)(hp + 64);
    float4 hb1 = *(const float4*)(hp + 68);
    float4 wv1 = *(const float4*)(wp + 32);

#pragma unroll 4
    for (int kl = 0; kl < 128; kl += 2) {
        {   // compute kl (slot 0)
            float2 h2[4] = { {ha0.x,ha0.y},{ha0.z,ha0.w},{hb0.x,hb0.y},{hb0.z,hb0.w} };
            float  wr[4] = { wv0.x, wv0.y, wv0.z, wv0.w };
#pragma unroll
            for (int r = 0; r < 4; r++) {
                float2 w2 = make_float2(wr[r], wr[r]);
#pragma unroll
                for (int j = 0; j < 4; j++) acc[r][j] = ffma2(h2[j], w2, acc[r][j]);
            }
        }
        int kn = (kl + 2 <= 126) ? kl + 2 : 126;      // clamped tail prefetch
        ha0 = *(const float4*)(hp + kn * 64);
        hb0 = *(const float4*)(hp + kn * 64 + 4);
        wv0 = *(const float4*)(wp + kn * 32);
        {   // compute kl+1 (slot 1)
            float2 h2[4] = { {ha1.x,ha1.y},{ha1.z,ha1.w},{hb1.x,hb1.y},{hb1.z,hb1.w} };
            float  wr[4] = { wv1.x, wv1.y, wv1.z, wv1.w };
#pragma unroll
            for (int r = 0; r < 4; r++) {
                float2 w2 = make_float2(wr[r], wr[r]);
#pragma unroll
                for (int j = 0; j < 4; j++) acc[r][j] = ffma2(h2[j], w2, acc[r][j]);
            }
        }
        int km = (kl + 3 <= 127) ? kl + 3 : 127;
        ha1 = *(const float4*)(hp + km * 64);
        hb1 = *(const float4*)(hp + km * 64 + 4);
        wv1 = *(const float4*)(wp + km * 32);
    }
}

// Write the warp's 32x32 partial into its own tile slice (padded EVEN stride).
__device__ __forceinline__ void write_partial(float2 (&acc)[4][4], float* part,
                                              int rg, int bg)
{
#pragma unroll
    for (int r = 0; r < 4; r++) {
        float* row = part + (rg * 4 + r) * PSTR + bg * 8;
#pragma unroll
        for (int j = 0; j < 4; j++) *(float2*)(row + j * 2) = acc[r][j];
    }
}

// =====================================================================
// Persistent kernel: CTA owns 8 hidden units (32 gate rows) for BOTH layers.
// 512 threads = 16 warps = 8 K-splits x 2 batch-halves.
// Release = grid_group::sync pattern (CTA barrier + tid0 cumulative fence).
// After the loop, CTA 0 computes the classifier (folded-in classify).
// =====================================================================
__global__ __launch_bounds__(512, 1) void lstm_persistent(
    const float* __restrict__ W0, const float* __restrict__ W1,
    const float* __restrict__ b1,
    const float* __restrict__ V, const float* __restrict__ bV,
    float* __restrict__ out)
{
    extern __shared__ float dsm[];    // 8 pair tiles of TILE_F floats

    const int tid   = threadIdx.x;
    const int w     = tid >> 5;
    const int lane  = tid & 31;
    const int s     = w >> 1;         // K-split 0..7
    const int hf    = w & 1;          // batch half
    const int pt    = tid & 63;       // pair-local thread
    const int rg    = lane >> 2;      // row group (4 rows)
    const int bg    = lane & 3;       // batch group (8 batch)
    const int cbase = blockIdx.x * 8;
    const int jl    = tid >> 6;       // cell phase: local hidden unit 0..7
    const int b     = tid & 63;       // cell phase: batch lane

    float* Wt   = dsm + s * TILE_F;
    float* part = Wt + hf * (32 * PSTR);
    const float* wp = Wt + rg * 4;
    const int hoff = hf * 32 + bg * 8;

    float c0 = 0.f, c1 = 0.f;         // register-resident cell state
    float b1r[4];
#pragma unroll
    for (int q = 0; q < 4; q++) b1r[q] = b1[q * HIDDEN + cbase + jl];

    for (int t = 0; t < T_STEPS; t++) {
        const int p = t & 1;
        const float* h0_old = g_h0buf[p];
        float*       h0_new = g_h0buf[p ^ 1];
        const float* h1_old = g_h1buf[p];
        float*       h1_new = g_h1buf[p ^ 1];

        // prefetch this thread's X0 gate values (DRAM latency hides under GEMM)
        const float* X0t = g_X0 + (size_t)t * G4 * BATCH;
        float x0r[4];
#pragma unroll
        for (int q = 0; q < 4; q++)
            x0r[q] = X0t[(size_t)(q * HIDDEN + cbase + jl) * BATCH + b];

        // ---- layer 0: gates = X0[t] + W0[:, E:E+H] @ h0_old ----
        float2 acc[4][4];
#pragma unroll
        for (int r = 0; r < 4; r++)
#pragma unroll
            for (int j = 0; j < 4; j++) acc[r][j] = make_float2(0.f, 0.f);

        stage_W(W0, EMBED + HIDDEN, EMBED + s * 128, cbase, Wt, pt);
        barp(s);
        gemm128(h0_old + (size_t)(s * 128) * 64 + hoff, wp, acc);
        barp(s);                      // pair done reading Wt -> alias as partials
        write_partial(acc, part, rg, bg);
        __syncthreads();
        {
            const float* pb = dsm + (b >> 5) * (32 * PSTR) + (b & 31);
            float gs[4];
#pragma unroll
            for (int q = 0; q < 4; q++) {
                float v = x0r[q];
#pragma unroll
                for (int ss = 0; ss < 8; ss++)
                    v += pb[ss * TILE_F + (q * 8 + jl) * PSTR];
                gs[q] = v;
            }
            float cn = sigf(gs[1]) * c0 + sigf(gs[0]) * tanh_fast(gs[2]);
            c0 = cn;
            h0_new[(cbase + jl) * BATCH + b] = sigf(gs[3]) * tanh_fast(cn);
        }
        __syncthreads();              // all h0_new stores happen-before tid0's fence
        if (tid == 0) { __threadfence(); atomicAdd(&g_cA, 1u); }

        // ---- layer 1: gates = b1 + W1 @ [h0_new ; h1_old] ----
        // Stage chunk 0's W BEFORE the counter wait (ctr_wait's barp publishes).
        // splits 0-3 (h0_new) wait on A; splits 4-7 (h1_old) wait on B.
#pragma unroll
        for (int r = 0; r < 4; r++)
#pragma unroll
            for (int j = 0; j < 4; j++) acc[r][j] = make_float2(0.f, 0.f);

        stage_W(W1, 2 * HIDDEN, s * 256, cbase, Wt, pt);
        const float* hsrc;
        if (s < 4) { ctr_wait(&g_cA, (unsigned)(t + 1) * NCTA, s, pt); hsrc = h0_new; }
        else       { ctr_wait(&g_cB, (unsigned)t * NCTA,       s, pt); hsrc = h1_old; }
        const int kb = (s & 3) * 256;
        gemm128(hsrc + (size_t)kb * 64 + hoff, wp, acc);
        barp(s);
        stage_W(W1, 2 * HIDDEN, s * 256 + 128, cbase, Wt, pt);
        barp(s);
        gemm128(hsrc + (size_t)(kb + 128) * 64 + hoff, wp, acc);
        barp(s);
        write_partial(acc, part, rg, bg);
        __syncthreads();
        {
            const float* pb = dsm + (b >> 5) * (32 * PSTR) + (b & 31);
            float gs[4];
#pragma unroll
            for (int q = 0; q < 4; q++) {
                float v = b1r[q];
#pragma unroll
                for (int ss = 0; ss < 8; ss++)
                    v += pb[ss * TILE_F + (q * 8 + jl) * PSTR];
                gs[q] = v;
            }
            float cn = sigf(gs[1]) * c1 + sigf(gs[0]) * tanh_fast(gs[2]);
            c1 = cn;
            h1_new[(cbase + jl) * BATCH + b] = sigf(gs[3]) * tanh_fast(cn);
        }
        __syncthreads();              // all h1_new stores happen-before tid0's fence
        if (tid == 0) { __threadfence(); atomicAdd(&g_cB, 1u); }
    }

    // ---- folded classifier: CTA 0 only, after ALL CTAs' final cB bump ----
    // out[b][c] = bV[c] + sum_j h1_final[j][b] * V[c][j]; h1_final = g_h1buf[0]
    if (blockIdx.x == 0) {
        if (tid == 0) {
            while (*(volatile unsigned*)&g_cB < (unsigned)T_STEPS * NCTA)
                { __nanosleep(64); }
            __threadfence();
        }
        __syncthreads();
        const int sl = tid >> 6;      // j-slice 0..7
        const float* hp = g_h1buf[0] + (size_t)sl * 128 * BATCH + b;
        for (int c = 0; c < NCLS; c++) {
            const float* vr = V + (size_t)c * HIDDEN + sl * 128;
            float a = 0.f;
#pragma unroll 8
            for (int j = 0; j < 128; j++) a += hp[j * BATCH] * vr[j];
            dsm[tid] = a;
            __syncthreads();
            if (tid < 64) {
                float ssum = bV[c];
#pragma unroll
                for (int k2 = 0; k2 < 8; k2++) ssum += dsm[k2 * 64 + tid];
                out[tid * NCLS + c] = ssum;
            }
            __syncthreads();
        }
    }
}

// =====================================================================
extern "C" void kernel_launch(void* const* d_in, const int* in_sizes, int n_in,
                              void* d_out, int out_size)
{
    (void)in_sizes; (void)n_in; (void)out_size;
    const int*   x   = (const int*)d_in[0];
    const float* emb = (const float*)d_in[1];
    const float* W0  = (const float*)d_in[2];
    const float* b0  = (const float*)d_in[3];
    const float* W1  = (const float*)d_in[4];
    const float* b1  = (const float*)d_in[5];
    const float* V   = (const float*)d_in[6];
    const float* bV  = (const float*)d_in[7];
    float* out = (float*)d_out;

    cudaFuncSetAttribute(lstm_persistent,
                         cudaFuncAttributeMaxDynamicSharedMemorySize, SMEM_BYTES);

    precompute_x0<<<dim3(T_STEPS, 64), 128>>>(x, emb, W0, b0);
    lstm_persistent<<<NCTA, 512, SMEM_BYTES>>>(W0, W1, b1, V, bV, out);
}